// round 15
// baseline (speedup 1.0000x reference)
#include <cuda_runtime.h>
#include <cuda_fp16.h>
#include <math.h>
#include <stdint.h>

#define BB   8
#define CC   256
#define NPIX 4096
#define NGRP 16
#define SCALE 0.0625f   /* 256^-0.5 */

/* ---- scratch (static device globals: allocation-free) ---- */
__device__ __half g_qT[(size_t)BB * NPIX * CC];   /* Q^T: [b][pixel][ch] */
__device__ __half g_kT[(size_t)BB * NPIX * CC];   /* K^T: [b][pixel][ch] */
__device__ __half g_v [(size_t)BB * CC * NPIX];   /* V:   [b][ch][pixel] */
__device__ float  g_y[2][BB * CC * 64];
__device__ float  g_s[2][BB * CC * 64];

__device__ __forceinline__ uint32_t h2u(__half2 h) {
    return *(uint32_t*)&h;
}
__device__ __forceinline__ void mma_f16(float* d,
                                        uint32_t a0, uint32_t a1, uint32_t a2, uint32_t a3,
                                        uint32_t b0, uint32_t b1) {
    asm volatile(
        "mma.sync.aligned.m16n8k16.row.col.f32.f16.f16.f32 "
        "{%0,%1,%2,%3}, {%4,%5,%6,%7}, {%8,%9}, {%0,%1,%2,%3};\n"
        : "+f"(d[0]), "+f"(d[1]), "+f"(d[2]), "+f"(d[3])
        : "r"(a0), "r"(a1), "r"(a2), "r"(a3), "r"(b0), "r"(b1));
}

/* ================= 1. row/col means ================= */
__global__ void __launch_bounds__(256) means_kernel(const float* __restrict__ x) {
    __shared__ float tile[64][65];
    int bc = blockIdx.x;
    const float* xp = x + (size_t)bc * NPIX;
    int tid = threadIdx.x;
    #pragma unroll
    for (int t = 0; t < 16; t++) {
        int idx = tid + t * 256;
        tile[idx >> 6][idx & 63] = xp[idx];
    }
    __syncthreads();
    if (tid < 64) {
        float s = 0.f;
        #pragma unroll
        for (int w = 0; w < 64; w++) s += tile[tid][w];
        g_y[0][(size_t)bc * 64 + tid] = s * (1.0f / 64.0f);
    } else if (tid < 128) {
        int w = tid - 64;
        float s = 0.f;
        #pragma unroll
        for (int h = 0; h < 64; h++) s += tile[h][w];
        g_y[1][(size_t)bc * 64 + w] = s * (1.0f / 64.0f);
    }
}

/* ================= 2. GN + sigmoid branch ================= */
__global__ void __launch_bounds__(256) gn_kernel(const float* __restrict__ w1,
                                                 const float* __restrict__ b1,
                                                 const float* __restrict__ gamma,
                                                 const float* __restrict__ beta) {
    extern __shared__ float sm[];
    float* ys  = sm;
    float* red = sm + 256 * 64;
    __shared__ float mu_s[NGRP], rs_s[NGRP];

    int br = blockIdx.x >> 3;
    int b  = blockIdx.x & 7;
    const float* y = g_y[br] + (size_t)b * CC * 64;
    int tid = threadIdx.x;

    #pragma unroll
    for (int t = 0; t < 16; t++) {
        int i4 = tid + t * 256;
        ((float4*)ys)[i4] = ((const float4*)y)[i4];
    }
    __syncthreads();

    float acc[64];
    #pragma unroll
    for (int l = 0; l < 64; l++) acc[l] = 0.f;

    const float* w1r = w1 + (size_t)tid * CC;
    for (int c = 0; c < CC; c++) {
        float wv = w1r[c];
        const float4* yr = (const float4*)(ys + c * 64);
        #pragma unroll
        for (int l4 = 0; l4 < 16; l4++) {
            float4 yv = yr[l4];
            acc[l4 * 4 + 0] += wv * yv.x;
            acc[l4 * 4 + 1] += wv * yv.y;
            acc[l4 * 4 + 2] += wv * yv.z;
            acc[l4 * 4 + 3] += wv * yv.w;
        }
    }
    float bias = b1[tid];
    float s1 = 0.f, s2 = 0.f;
    #pragma unroll
    for (int l = 0; l < 64; l++) {
        acc[l] += bias;
        s1 += acc[l];
        s2 += acc[l] * acc[l];
    }
    red[tid]       = s1;
    red[256 + tid] = s2;
    __syncthreads();
    if (tid < NGRP) {
        float S = 0.f, S2 = 0.f;
        #pragma unroll
        for (int k = 0; k < 16; k++) {
            S  += red[tid * 16 + k];
            S2 += red[256 + tid * 16 + k];
        }
        float mu  = S * (1.0f / 1024.0f);
        float var = S2 * (1.0f / 1024.0f) - mu * mu;
        mu_s[tid] = mu;
        rs_s[tid] = rsqrtf(var + 1e-5f);
    }
    __syncthreads();
    float mu = mu_s[tid >> 4], rs = rs_s[tid >> 4];
    float ga = gamma[tid], be = beta[tid];
    float* o = g_s[br] + ((size_t)b * CC + tid) * 64;
    #pragma unroll
    for (int l = 0; l < 64; l++) {
        float zn = (acc[l] - mu) * rs;
        float v  = zn * ga + be;
        o[l] = 1.0f / (1.0f + __expf(-v));
    }
}

/* ================= 3. QKV projection (fp16 tensor-core GEMM) =============== */
#define WPH 264
#define QKV_SMEM (2 * 128 * WPH * 2)     /* 135168 B */

__global__ void __launch_bounds__(256) qkv_kernel(const float* __restrict__ x,
                                                  const float* __restrict__ wq) {
    extern __shared__ __half smh[];
    __half* Ws = smh;                 /* [128][WPH] */
    __half* Xs = smh + 128 * WPH;     /* [128 n][WPH k] */
    int mtb = blockIdx.x, ntb = blockIdx.y, b = blockIdx.z;
    int m0 = mtb * 128, n0 = ntb * 128;
    const float* X = x + (size_t)b * CC * NPIX;
    int tid = threadIdx.x;
    int lane = tid & 31, wid = tid >> 5;
    int g = lane >> 2, t = lane & 3;

    {
        int row = tid >> 1, ks = (tid & 1) * 128;
        const float* src = wq + (size_t)(m0 + row) * CC + ks;
        __half* dst = Ws + row * WPH + ks;
        #pragma unroll
        for (int i = 0; i < 32; i++) {
            float4 w = *(const float4*)(src + i * 4);
            uint2 p;
            p.x = h2u(__floats2half2_rn(w.x, w.y));
            p.y = h2u(__floats2half2_rn(w.z, w.w));
            *(uint2*)(dst + i * 4) = p;
        }
    }
    {
        int kg = tid >> 3;
        int nI = (tid & 7) * 4;
        #pragma unroll
        for (int it = 0; it < 8; it++) {
            int k = kg + it * 32;
            const float* src = X + (size_t)k * NPIX + n0 + nI;
            #pragma unroll
            for (int jj = 0; jj < 4; jj++) {
                float4 v = *(const float4*)(src + jj * 32);
                int n = nI + jj * 32;
                Xs[(n + 0) * WPH + k] = __float2half_rn(v.x);
                Xs[(n + 1) * WPH + k] = __float2half_rn(v.y);
                Xs[(n + 2) * WPH + k] = __float2half_rn(v.z);
                Xs[(n + 3) * WPH + k] = __float2half_rn(v.w);
            }
        }
    }
    __syncthreads();

    int wm = wid & 1, wn = wid >> 1;
    int mw0 = wm * 64, nw0 = wn * 32;

    float acc[4][4][4];
    #pragma unroll
    for (int mt = 0; mt < 4; mt++)
        #pragma unroll
        for (int nt = 0; nt < 4; nt++)
            #pragma unroll
            for (int e = 0; e < 4; e++) acc[mt][nt][e] = 0.f;

    #pragma unroll 4
    for (int ks = 0; ks < 16; ks++) {
        uint32_t bf[4][2];
        #pragma unroll
        for (int nt = 0; nt < 4; nt++) {
            const __half* bp = Xs + (nw0 + nt * 8 + g) * WPH + ks * 16 + 2 * t;
            bf[nt][0] = *(const uint32_t*)bp;
            bf[nt][1] = *(const uint32_t*)(bp + 8);
        }
        #pragma unroll
        for (int mt = 0; mt < 4; mt++) {
            const __half* ap = Ws + (mw0 + mt * 16 + g) * WPH + ks * 16 + 2 * t;
            uint32_t a0 = *(const uint32_t*)ap;
            uint32_t a1 = *(const uint32_t*)(ap + 8 * WPH);
            uint32_t a2 = *(const uint32_t*)(ap + 8);
            uint32_t a3 = *(const uint32_t*)(ap + 8 * WPH + 8);
            #pragma unroll
            for (int nt = 0; nt < 4; nt++)
                mma_f16(acc[mt][nt], a0, a1, a2, a3, bf[nt][0], bf[nt][1]);
        }
    }

    if (m0 < 512) {
        __half* dstb = (m0 < 256 ? g_qT : g_kT) + (size_t)b * NPIX * CC;
        int chb = (m0 & 255) + mw0;
        #pragma unroll
        for (int mt = 0; mt < 4; mt++) {
            int ch = chb + mt * 16 + g;
            #pragma unroll
            for (int nt = 0; nt < 4; nt++) {
                int n = n0 + nw0 + nt * 8 + 2 * t;
                dstb[(size_t)n * CC + ch]           = __float2half_rn(acc[mt][nt][0]);
                dstb[(size_t)(n + 1) * CC + ch]     = __float2half_rn(acc[mt][nt][1]);
                dstb[(size_t)n * CC + ch + 8]       = __float2half_rn(acc[mt][nt][2]);
                dstb[(size_t)(n + 1) * CC + ch + 8] = __float2half_rn(acc[mt][nt][3]);
            }
        }
    } else {
        __half* dstb = g_v + (size_t)b * CC * NPIX;
        int chb = (m0 - 512) + mw0;
        #pragma unroll
        for (int mt = 0; mt < 4; mt++) {
            int ch = chb + mt * 16 + g;
            #pragma unroll
            for (int nt = 0; nt < 4; nt++) {
                int n = n0 + nw0 + nt * 8 + 2 * t;
                *(__half2*)(dstb + (size_t)ch * NPIX + n) =
                    __floats2half2_rn(acc[mt][nt][0], acc[mt][nt][1]);
                *(__half2*)(dstb + (size_t)(ch + 8) * NPIX + n) =
                    __floats2half2_rn(acc[mt][nt][2], acc[mt][nt][3]);
            }
        }
    }
}

/* ================= 4. flash attention (1024 threads, 32 warps) =============
   grid (64, 8); block 1024 = 32 warps, warp grid 4(row) x 8(col).
   BN=128 K-tiles, 32 iterations; fixed-max softmax; 3 barriers/iter.
   Per warp: S 16x16 (sacc[2][4]); PV 16 rows x 32 d (o[4][4]).            */
#define QPH 264   /* halves */
#define KPH 264
#define VPH 136
#define PPH 136
#define SM_Q   0                                 /* 64*264*2   = 33792 */
#define SM_K   33792                             /* 128*264*2  = 67584 */
#define SM_V   101376                            /* 256*136*2  = 69632 */
#define SM_P   171008                            /* 64*136*2   = 17408 */
#define SM_SPB 188416                            /* float[8][64] = 2048 */
#define ATT_SMEM 190464

__device__ __forceinline__ void cp16h(void* dst_smem, const void* src) {
    uint32_t d = (uint32_t)__cvta_generic_to_shared(dst_smem);
    asm volatile("cp.async.cg.shared.global [%0], [%1], 16;" :: "r"(d), "l"(src));
}
#define CP_COMMIT() asm volatile("cp.async.commit_group;" ::: "memory")
#define CP_WAIT1()  asm volatile("cp.async.wait_group 1;" ::: "memory")
#define CP_WAIT0()  asm volatile("cp.async.wait_group 0;" ::: "memory")

__global__ void __launch_bounds__(1024) flash_kernel(const float* __restrict__ x,
                                                     float* __restrict__ out) {
    extern __shared__ char smc[];
    __half* QsT = (__half*)(smc + SM_Q);
    __half* KsT = (__half*)(smc + SM_K);
    __half* Vs  = (__half*)(smc + SM_V);
    __half* Ps  = (__half*)(smc + SM_P);
    float* spart = (float*)(smc + SM_SPB);

    int qt = blockIdx.x, b = blockIdx.y;
    int n0 = qt * 64;
    const __half* qTg = g_qT + (size_t)b * NPIX * CC;
    const __half* kTg = g_kT + (size_t)b * NPIX * CC;
    const __half* vg  = g_v  + (size_t)b * CC * NPIX;

    int tid  = threadIdx.x;
    int lane = tid & 31;
    int wid  = tid >> 5;
    int g = lane >> 2, t = lane & 3;
    int wr = wid & 3, wc = wid >> 2;          /* wc 0..7 */
    int m0  = wr * 16;
    int nn0 = wc * 16;
    int d0  = wc * 32;

    /* prefetch Q tile + K(0) tile (one group) */
    #pragma unroll
    for (int it = 0; it < 2; it++) {
        int idx = tid + it * 1024;
        int r = idx >> 5, ch = idx & 31;
        cp16h(QsT + r * QPH + ch * 8, qTg + (size_t)(n0 + r) * CC + ch * 8);
    }
    #pragma unroll
    for (int it = 0; it < 4; it++) {
        int idx = tid + it * 1024;
        int r = idx >> 5, ch = idx & 31;
        cp16h(KsT + r * KPH + ch * 8, kTg + (size_t)r * CC + ch * 8);
    }
    CP_COMMIT();

    float o[4][4];
    #pragma unroll
    for (int nt = 0; nt < 4; nt++)
        #pragma unroll
        for (int e = 0; e < 4; e++) o[nt][e] = 0.f;
    float ps0acc = 0.f, ps1acc = 0.f;

    int r0 = m0 + g, r1 = r0 + 8;

    for (int kt = 0; kt < 32; kt++) {
        int km0 = kt * 128;
        __syncthreads();                       /* A: prev PV done; V/Ps free */

        /* issue V(kt) — overlaps with S phase */
        #pragma unroll
        for (int it = 0; it < 4; it++) {
            int idx = tid + it * 1024;
            int d = idx >> 4, ch = idx & 15;
            cp16h(Vs + d * VPH + ch * 8, vg + (size_t)d * NPIX + km0 + ch * 8);
        }
        CP_COMMIT();
        CP_WAIT1();                            /* K(kt) arrived */
        __syncthreads();                       /* B: K visible */

        /* ---- S = Q^T K: 16 rows x 16 cols per warp ---- */
        float sacc[2][4];
        #pragma unroll
        for (int nt = 0; nt < 2; nt++)
            #pragma unroll
            for (int e = 0; e < 4; e++) sacc[nt][e] = 0.f;

        #pragma unroll 8
        for (int ks = 0; ks < 16; ks++) {
            const __half* qa = QsT + (m0 + g) * QPH + ks * 16 + 2 * t;
            uint32_t a0 = *(const uint32_t*)qa;
            uint32_t a1 = *(const uint32_t*)(qa + 8 * QPH);
            uint32_t a2 = *(const uint32_t*)(qa + 8);
            uint32_t a3 = *(const uint32_t*)(qa + 8 * QPH + 8);
            #pragma unroll
            for (int nt = 0; nt < 2; nt++) {
                const __half* kb = KsT + (nn0 + nt * 8 + g) * KPH + ks * 16 + 2 * t;
                mma_f16(sacc[nt], a0, a1, a2, a3,
                        *(const uint32_t*)kb, *(const uint32_t*)(kb + 8));
            }
        }

        /* ---- fixed-max softmax: p = exp(SCALE*s) ---- */
        #pragma unroll
        for (int nt = 0; nt < 2; nt++) {
            int col = nn0 + nt * 8 + 2 * t;
            __half2 h0 = __floats2half2_rn(__expf(SCALE * sacc[nt][0]),
                                           __expf(SCALE * sacc[nt][1]));
            __half2 h1 = __floats2half2_rn(__expf(SCALE * sacc[nt][2]),
                                           __expf(SCALE * sacc[nt][3]));
            *(__half2*)(Ps + r0 * PPH + col) = h0;
            *(__half2*)(Ps + r1 * PPH + col) = h1;
            float2 f0 = __half22float2(h0);
            float2 f1 = __half22float2(h1);
            ps0acc += f0.x + f0.y;
            ps1acc += f1.x + f1.y;
        }

        CP_WAIT0();                            /* V(kt) arrived */
        __syncthreads();                       /* D: Ps + V visible; K consumed */

        /* issue K(kt+1) — overlaps PV */
        {
            int kn = (kt + 1 < 32) ? (kt + 1) * 128 : 0;
            #pragma unroll
            for (int it = 0; it < 4; it++) {
                int idx = tid + it * 1024;
                int r = idx >> 5, ch = idx & 31;
                cp16h(KsT + r * KPH + ch * 8, kTg + (size_t)(kn + r) * CC + ch * 8);
            }
            CP_COMMIT();
        }

        /* ---- PV mma (K-dim 128): 16 rows x 32 d per warp ---- */
        #pragma unroll
        for (int ks = 0; ks < 8; ks++) {
            const __half* pa = Ps + (m0 + g) * PPH + ks * 16 + 2 * t;
            uint32_t ua0 = *(const uint32_t*)pa;
            uint32_t ua1 = *(const uint32_t*)(pa + 8 * PPH);
            uint32_t ua2 = *(const uint32_t*)(pa + 8);
            uint32_t ua3 = *(const uint32_t*)(pa + 8 * PPH + 8);
            #pragma unroll
            for (int nt = 0; nt < 4; nt++) {
                const __half* vb = Vs + (d0 + nt * 8 + g) * VPH + ks * 16 + 2 * t;
                mma_f16(o[nt], ua0, ua1, ua2, ua3,
                        *(const uint32_t*)vb, *(const uint32_t*)(vb + 8));
            }
        }
    }

    /* final row-sum reduce: over t lanes, then over 8 warp-columns */
    ps0acc += __shfl_xor_sync(0xffffffffu, ps0acc, 1);
    ps0acc += __shfl_xor_sync(0xffffffffu, ps0acc, 2);
    ps1acc += __shfl_xor_sync(0xffffffffu, ps1acc, 1);
    ps1acc += __shfl_xor_sync(0xffffffffu, ps1acc, 2);
    __syncthreads();
    if (t == 0) { spart[wc * 64 + r0] = ps0acc; spart[wc * 64 + r1] = ps1acc; }
    __syncthreads();
    float l0 = 0.f, l1 = 0.f;
    #pragma unroll
    for (int j = 0; j < 8; j++) {
        l0 += spart[j * 64 + r0];
        l1 += spart[j * 64 + r1];
    }
    float il0 = 1.0f / l0;
    float il1 = 1.0f / l1;

    /* epilogue: normalize, add ELA, store */
    const float* xg = x + (size_t)b * CC * NPIX;
    float* og = out + (size_t)b * CC * NPIX;
    int i0 = m0 + g, i1 = i0 + 8;     /* w coords; h = qt */
    #pragma unroll
    for (int nt = 0; nt < 4; nt++) {
        #pragma unroll
        for (int bc = 0; bc < 2; bc++) {
            int d = d0 + nt * 8 + 2 * t + bc;
            float xh  = g_s[0][((size_t)b * CC + d) * 64 + qt];
            float xw0 = g_s[1][((size_t)b * CC + d) * 64 + i0];
            float xw1 = g_s[1][((size_t)b * CC + d) * 64 + i1];
            size_t base = (size_t)d * NPIX + n0;
            og[base + i0] = o[nt][bc]     * il0 + xg[base + i0] * xh * xw0;
            og[base + i1] = o[nt][2 + bc] * il1 + xg[base + i1] * xh * xw1;
        }
    }
}

/* ================= launch ================= */
extern "C" void kernel_launch(void* const* d_in, const int* in_sizes, int n_in,
                              void* d_out, int out_size) {
    const float* x     = (const float*)d_in[0];
    const float* wqkv  = (const float*)d_in[1];
    const float* w1    = (const float*)d_in[2];
    const float* b1    = (const float*)d_in[3];
    const float* gamma = (const float*)d_in[4];
    const float* beta  = (const float*)d_in[5];
    float* out = (float*)d_out;

    cudaFuncSetAttribute(gn_kernel, cudaFuncAttributeMaxDynamicSharedMemorySize,
                         (256 * 64 + 512) * 4);
    cudaFuncSetAttribute(qkv_kernel, cudaFuncAttributeMaxDynamicSharedMemorySize,
                         QKV_SMEM);
    cudaFuncSetAttribute(flash_kernel, cudaFuncAttributeMaxDynamicSharedMemorySize,
                         ATT_SMEM);

    means_kernel<<<BB * CC, 256>>>(x);
    gn_kernel<<<16, 256, (256 * 64 + 512) * 4>>>(w1, b1, gamma, beta);
    qkv_kernel<<<dim3(6, 32, BB), 256, QKV_SMEM>>>(x, wqkv);
    flash_kernel<<<dim3(64, BB), 1024, ATT_SMEM>>>(x, out);
}

// round 16
// speedup vs baseline: 1.1477x; 1.1477x over previous
#include <cuda_runtime.h>
#include <cuda_fp16.h>
#include <math.h>
#include <stdint.h>

#define BB   8
#define CC   256
#define NPIX 4096
#define NGRP 16
#define SCALE 0.0625f   /* 256^-0.5 */

/* ---- scratch (static device globals: allocation-free) ---- */
__device__ __half g_qT[(size_t)BB * NPIX * CC];   /* Q^T: [b][pixel][ch] */
__device__ __half g_kT[(size_t)BB * NPIX * CC];   /* K^T: [b][pixel][ch] */
__device__ __half g_v [(size_t)BB * CC * NPIX];   /* V:   [b][ch][pixel] */
__device__ float  g_y[2][BB * CC * 64];
__device__ float  g_s[2][BB * CC * 64];

__device__ __forceinline__ uint32_t h2u(__half2 h) {
    return *(uint32_t*)&h;
}
__device__ __forceinline__ void mma_f16(float* d,
                                        uint32_t a0, uint32_t a1, uint32_t a2, uint32_t a3,
                                        uint32_t b0, uint32_t b1) {
    asm volatile(
        "mma.sync.aligned.m16n8k16.row.col.f32.f16.f16.f32 "
        "{%0,%1,%2,%3}, {%4,%5,%6,%7}, {%8,%9}, {%0,%1,%2,%3};\n"
        : "+f"(d[0]), "+f"(d[1]), "+f"(d[2]), "+f"(d[3])
        : "r"(a0), "r"(a1), "r"(a2), "r"(a3), "r"(b0), "r"(b1));
}
__device__ __forceinline__ void ldsm4(uint32_t* r, uint32_t saddr) {
    asm volatile(
        "ldmatrix.sync.aligned.m8n8.x4.shared.b16 {%0,%1,%2,%3}, [%4];"
        : "=r"(r[0]), "=r"(r[1]), "=r"(r[2]), "=r"(r[3]) : "r"(saddr));
}
__device__ __forceinline__ uint32_t sptr(const void* p) {
    return (uint32_t)__cvta_generic_to_shared(p);
}

/* ================= 1. row/col means ================= */
__global__ void __launch_bounds__(256) means_kernel(const float* __restrict__ x) {
    __shared__ float tile[64][65];
    int bc = blockIdx.x;
    const float* xp = x + (size_t)bc * NPIX;
    int tid = threadIdx.x;
    #pragma unroll
    for (int t = 0; t < 16; t++) {
        int idx = tid + t * 256;
        tile[idx >> 6][idx & 63] = xp[idx];
    }
    __syncthreads();
    if (tid < 64) {
        float s = 0.f;
        #pragma unroll
        for (int w = 0; w < 64; w++) s += tile[tid][w];
        g_y[0][(size_t)bc * 64 + tid] = s * (1.0f / 64.0f);
    } else if (tid < 128) {
        int w = tid - 64;
        float s = 0.f;
        #pragma unroll
        for (int h = 0; h < 64; h++) s += tile[h][w];
        g_y[1][(size_t)bc * 64 + w] = s * (1.0f / 64.0f);
    }
}

/* ================= 2. GN + sigmoid branch ================= */
__global__ void __launch_bounds__(256) gn_kernel(const float* __restrict__ w1,
                                                 const float* __restrict__ b1,
                                                 const float* __restrict__ gamma,
                                                 const float* __restrict__ beta) {
    extern __shared__ float sm[];
    float* ys  = sm;
    float* red = sm + 256 * 64;
    __shared__ float mu_s[NGRP], rs_s[NGRP];

    int br = blockIdx.x >> 3;
    int b  = blockIdx.x & 7;
    const float* y = g_y[br] + (size_t)b * CC * 64;
    int tid = threadIdx.x;

    #pragma unroll
    for (int t = 0; t < 16; t++) {
        int i4 = tid + t * 256;
        ((float4*)ys)[i4] = ((const float4*)y)[i4];
    }
    __syncthreads();

    float acc[64];
    #pragma unroll
    for (int l = 0; l < 64; l++) acc[l] = 0.f;

    const float* w1r = w1 + (size_t)tid * CC;
    for (int c = 0; c < CC; c++) {
        float wv = w1r[c];
        const float4* yr = (const float4*)(ys + c * 64);
        #pragma unroll
        for (int l4 = 0; l4 < 16; l4++) {
            float4 yv = yr[l4];
            acc[l4 * 4 + 0] += wv * yv.x;
            acc[l4 * 4 + 1] += wv * yv.y;
            acc[l4 * 4 + 2] += wv * yv.z;
            acc[l4 * 4 + 3] += wv * yv.w;
        }
    }
    float bias = b1[tid];
    float s1 = 0.f, s2 = 0.f;
    #pragma unroll
    for (int l = 0; l < 64; l++) {
        acc[l] += bias;
        s1 += acc[l];
        s2 += acc[l] * acc[l];
    }
    red[tid]       = s1;
    red[256 + tid] = s2;
    __syncthreads();
    if (tid < NGRP) {
        float S = 0.f, S2 = 0.f;
        #pragma unroll
        for (int k = 0; k < 16; k++) {
            S  += red[tid * 16 + k];
            S2 += red[256 + tid * 16 + k];
        }
        float mu  = S * (1.0f / 1024.0f);
        float var = S2 * (1.0f / 1024.0f) - mu * mu;
        mu_s[tid] = mu;
        rs_s[tid] = rsqrtf(var + 1e-5f);
    }
    __syncthreads();
    float mu = mu_s[tid >> 4], rs = rs_s[tid >> 4];
    float ga = gamma[tid], be = beta[tid];
    float* o = g_s[br] + ((size_t)b * CC + tid) * 64;
    #pragma unroll
    for (int l = 0; l < 64; l++) {
        float zn = (acc[l] - mu) * rs;
        float v  = zn * ga + be;
        o[l] = 1.0f / (1.0f + __expf(-v));
    }
}

/* ================= 3. QKV projection (fp16 tensor-core GEMM) =============== */
#define WPH 264
#define QKV_SMEM (2 * 128 * WPH * 2)     /* 135168 B */

__global__ void __launch_bounds__(256) qkv_kernel(const float* __restrict__ x,
                                                  const float* __restrict__ wq) {
    extern __shared__ __half smh[];
    __half* Ws = smh;                 /* [128][WPH] */
    __half* Xs = smh + 128 * WPH;     /* [128 n][WPH k] */
    int mtb = blockIdx.x, ntb = blockIdx.y, b = blockIdx.z;
    int m0 = mtb * 128, n0 = ntb * 128;
    const float* X = x + (size_t)b * CC * NPIX;
    int tid = threadIdx.x;
    int lane = tid & 31, wid = tid >> 5;
    int g = lane >> 2, t = lane & 3;

    {
        int row = tid >> 1, ks = (tid & 1) * 128;
        const float* src = wq + (size_t)(m0 + row) * CC + ks;
        __half* dst = Ws + row * WPH + ks;
        #pragma unroll
        for (int i = 0; i < 32; i++) {
            float4 w = *(const float4*)(src + i * 4);
            uint2 p;
            p.x = h2u(__floats2half2_rn(w.x, w.y));
            p.y = h2u(__floats2half2_rn(w.z, w.w));
            *(uint2*)(dst + i * 4) = p;
        }
    }
    {
        int kg = tid >> 3;
        int nI = (tid & 7) * 4;
        #pragma unroll
        for (int it = 0; it < 8; it++) {
            int k = kg + it * 32;
            const float* src = X + (size_t)k * NPIX + n0 + nI;
            #pragma unroll
            for (int jj = 0; jj < 4; jj++) {
                float4 v = *(const float4*)(src + jj * 32);
                int n = nI + jj * 32;
                Xs[(n + 0) * WPH + k] = __float2half_rn(v.x);
                Xs[(n + 1) * WPH + k] = __float2half_rn(v.y);
                Xs[(n + 2) * WPH + k] = __float2half_rn(v.z);
                Xs[(n + 3) * WPH + k] = __float2half_rn(v.w);
            }
        }
    }
    __syncthreads();

    int wm = wid & 1, wn = wid >> 1;
    int mw0 = wm * 64, nw0 = wn * 32;

    float acc[4][4][4];
    #pragma unroll
    for (int mt = 0; mt < 4; mt++)
        #pragma unroll
        for (int nt = 0; nt < 4; nt++)
            #pragma unroll
            for (int e = 0; e < 4; e++) acc[mt][nt][e] = 0.f;

    #pragma unroll 4
    for (int ks = 0; ks < 16; ks++) {
        uint32_t bf[4][2];
        #pragma unroll
        for (int nt = 0; nt < 4; nt++) {
            const __half* bp = Xs + (nw0 + nt * 8 + g) * WPH + ks * 16 + 2 * t;
            bf[nt][0] = *(const uint32_t*)bp;
            bf[nt][1] = *(const uint32_t*)(bp + 8);
        }
        #pragma unroll
        for (int mt = 0; mt < 4; mt++) {
            const __half* ap = Ws + (mw0 + mt * 16 + g) * WPH + ks * 16 + 2 * t;
            uint32_t a0 = *(const uint32_t*)ap;
            uint32_t a1 = *(const uint32_t*)(ap + 8 * WPH);
            uint32_t a2 = *(const uint32_t*)(ap + 8);
            uint32_t a3 = *(const uint32_t*)(ap + 8 * WPH + 8);
            #pragma unroll
            for (int nt = 0; nt < 4; nt++)
                mma_f16(acc[mt][nt], a0, a1, a2, a3, bf[nt][0], bf[nt][1]);
        }
    }

    if (m0 < 512) {
        __half* dstb = (m0 < 256 ? g_qT : g_kT) + (size_t)b * NPIX * CC;
        int chb = (m0 & 255) + mw0;
        #pragma unroll
        for (int mt = 0; mt < 4; mt++) {
            int ch = chb + mt * 16 + g;
            #pragma unroll
            for (int nt = 0; nt < 4; nt++) {
                int n = n0 + nw0 + nt * 8 + 2 * t;
                dstb[(size_t)n * CC + ch]           = __float2half_rn(acc[mt][nt][0]);
                dstb[(size_t)(n + 1) * CC + ch]     = __float2half_rn(acc[mt][nt][1]);
                dstb[(size_t)n * CC + ch + 8]       = __float2half_rn(acc[mt][nt][2]);
                dstb[(size_t)(n + 1) * CC + ch + 8] = __float2half_rn(acc[mt][nt][3]);
            }
        }
    } else {
        __half* dstb = g_v + (size_t)b * CC * NPIX;
        int chb = (m0 - 512) + mw0;
        #pragma unroll
        for (int mt = 0; mt < 4; mt++) {
            int ch = chb + mt * 16 + g;
            #pragma unroll
            for (int nt = 0; nt < 4; nt++) {
                int n = n0 + nw0 + nt * 8 + 2 * t;
                *(__half2*)(dstb + (size_t)ch * NPIX + n) =
                    __floats2half2_rn(acc[mt][nt][0], acc[mt][nt][1]);
                *(__half2*)(dstb + (size_t)(ch + 8) * NPIX + n) =
                    __floats2half2_rn(acc[mt][nt][2], acc[mt][nt][3]);
            }
        }
    }
}

/* ================= 4. flash attention (512 thr, ldmatrix fragments) ========
   grid (64, 8); block 512 = 16 warps, warp grid 4(row) x 4(col).
   BN=128 K-tiles, 32 iterations; fixed-max softmax; 3 barriers/iter.
   All MMA fragments loaded via ldmatrix.m8n8.x4 (same bytes, 1/4 the
   instructions; pitches give bank = row*4 mod 32 => conflict-free).       */
#define QPH 264   /* halves */
#define KPH 264
#define VPH 136
#define PPH 136
#define SM_Q   0                                 /* 64*264*2   = 33792 */
#define SM_K   33792                             /* 128*264*2  = 67584 */
#define SM_V   101376                            /* 256*136*2  = 69632 */
#define SM_P   171008                            /* 64*136*2   = 17408 */
#define SM_SPB 188416                            /* float[4][64] = 1024 */
#define ATT_SMEM 189440

__device__ __forceinline__ void cp16h(void* dst_smem, const void* src) {
    uint32_t d = (uint32_t)__cvta_generic_to_shared(dst_smem);
    asm volatile("cp.async.cg.shared.global [%0], [%1], 16;" :: "r"(d), "l"(src));
}
#define CP_COMMIT() asm volatile("cp.async.commit_group;" ::: "memory")
#define CP_WAIT1()  asm volatile("cp.async.wait_group 1;" ::: "memory")
#define CP_WAIT0()  asm volatile("cp.async.wait_group 0;" ::: "memory")

__global__ void __launch_bounds__(512) flash_kernel(const float* __restrict__ x,
                                                    float* __restrict__ out) {
    extern __shared__ char smc[];
    __half* QsT = (__half*)(smc + SM_Q);
    __half* KsT = (__half*)(smc + SM_K);
    __half* Vs  = (__half*)(smc + SM_V);
    __half* Ps  = (__half*)(smc + SM_P);
    float* spart = (float*)(smc + SM_SPB);

    int qt = blockIdx.x, b = blockIdx.y;
    int n0 = qt * 64;
    const __half* qTg = g_qT + (size_t)b * NPIX * CC;
    const __half* kTg = g_kT + (size_t)b * NPIX * CC;
    const __half* vg  = g_v  + (size_t)b * CC * NPIX;

    int tid  = threadIdx.x;
    int lane = tid & 31;
    int wid  = tid >> 5;
    int g = lane >> 2, t = lane & 3;
    int wr = wid & 3, wc = wid >> 2;
    int m0  = wr * 16;
    int nn0 = wc * 32;
    int d0  = wc * 64;

    /* ldmatrix lane-address components (lane-fixed, computed once) */
    int lrow8 = lane & 7;              /* row within 8x8 tile       */
    int lrhi  = (lane >> 3) & 1;       /* A: row+8 | B: col+8       */
    int lchi  = lane >> 4;             /* A: col+8 | B: row+8       */

    /* A-style frag (rows m, k): tiles (r,k0),(r+8,k0),(r,k8),(r+8,k8) */
    uint32_t aQbase = sptr(QsT + (m0 + lrow8 + lrhi * 8) * QPH + lchi * 8);
    uint32_t aPbase = sptr(Ps  + (m0 + lrow8 + lrhi * 8) * PPH + lchi * 8);
    /* B-style frag (rows n, k): tiles (n,k0),(n,k8),(n+8,k0),(n+8,k8) */
    uint32_t bKbase0 = sptr(KsT + (nn0 +  0 + lchi * 8 + lrow8) * KPH + lrhi * 8);
    uint32_t bKbase1 = sptr(KsT + (nn0 + 16 + lchi * 8 + lrow8) * KPH + lrhi * 8);
    uint32_t bVbase[4];
    #pragma unroll
    for (int vp = 0; vp < 4; vp++)
        bVbase[vp] = sptr(Vs + (d0 + vp * 16 + lchi * 8 + lrow8) * VPH + lrhi * 8);

    /* prefetch Q tile + K(0) tile (one group) */
    #pragma unroll
    for (int it = 0; it < 4; it++) {
        int idx = tid + it * 512;
        int r = idx >> 5, ch = idx & 31;
        cp16h(QsT + r * QPH + ch * 8, qTg + (size_t)(n0 + r) * CC + ch * 8);
    }
    #pragma unroll
    for (int it = 0; it < 8; it++) {
        int idx = tid + it * 512;
        int r = idx >> 5, ch = idx & 31;
        cp16h(KsT + r * KPH + ch * 8, kTg + (size_t)r * CC + ch * 8);
    }
    CP_COMMIT();

    float o[8][4];
    #pragma unroll
    for (int nt = 0; nt < 8; nt++)
        #pragma unroll
        for (int e = 0; e < 4; e++) o[nt][e] = 0.f;
    float ps0acc = 0.f, ps1acc = 0.f;

    int r0 = m0 + g, r1 = r0 + 8;

    for (int kt = 0; kt < 32; kt++) {
        int km0 = kt * 128;
        __syncthreads();                       /* A: prev PV done; V/Ps free */

        /* issue V(kt) — overlaps with S phase */
        #pragma unroll
        for (int it = 0; it < 8; it++) {
            int idx = tid + it * 512;
            int d = idx >> 4, ch = idx & 15;
            cp16h(Vs + d * VPH + ch * 8, vg + (size_t)d * NPIX + km0 + ch * 8);
        }
        CP_COMMIT();
        CP_WAIT1();                            /* K(kt) arrived */
        __syncthreads();                       /* B: K visible to all warps */

        /* ---- S = Q^T K: 16 rows x 32 cols per warp, ldmatrix frags ---- */
        float sacc[4][4];
        #pragma unroll
        for (int nt = 0; nt < 4; nt++)
            #pragma unroll
            for (int e = 0; e < 4; e++) sacc[nt][e] = 0.f;

        #pragma unroll 8
        for (int ks = 0; ks < 16; ks++) {
            uint32_t a[4], b0[4], b1[4];
            ldsm4(a,  aQbase  + ks * 32);
            ldsm4(b0, bKbase0 + ks * 32);
            ldsm4(b1, bKbase1 + ks * 32);
            mma_f16(sacc[0], a[0], a[1], a[2], a[3], b0[0], b0[1]);
            mma_f16(sacc[1], a[0], a[1], a[2], a[3], b0[2], b0[3]);
            mma_f16(sacc[2], a[0], a[1], a[2], a[3], b1[0], b1[1]);
            mma_f16(sacc[3], a[0], a[1], a[2], a[3], b1[2], b1[3]);
        }

        /* ---- fixed-max softmax: p = exp(SCALE*s) ---- */
        #pragma unroll
        for (int nt = 0; nt < 4; nt++) {
            int col = nn0 + nt * 8 + 2 * t;
            __half2 h0 = __floats2half2_rn(__expf(SCALE * sacc[nt][0]),
                                           __expf(SCALE * sacc[nt][1]));
            __half2 h1 = __floats2half2_rn(__expf(SCALE * sacc[nt][2]),
                                           __expf(SCALE * sacc[nt][3]));
            *(__half2*)(Ps + r0 * PPH + col) = h0;
            *(__half2*)(Ps + r1 * PPH + col) = h1;
            float2 f0 = __half22float2(h0);
            float2 f1 = __half22float2(h1);
            ps0acc += f0.x + f0.y;
            ps1acc += f1.x + f1.y;
        }

        CP_WAIT0();                            /* V(kt) arrived */
        __syncthreads();                       /* D: Ps + V visible; K consumed */

        /* issue K(kt+1) — overlaps PV */
        {
            int kn = (kt + 1 < 32) ? (kt + 1) * 128 : 0;
            #pragma unroll
            for (int it = 0; it < 8; it++) {
                int idx = tid + it * 512;
                int r = idx >> 5, ch = idx & 31;
                cp16h(KsT + r * KPH + ch * 8, kTg + (size_t)(kn + r) * CC + ch * 8);
            }
            CP_COMMIT();
        }

        /* ---- PV mma (K-dim 128), ldmatrix frags ---- */
        #pragma unroll
        for (int ks = 0; ks < 8; ks++) {
            uint32_t ua[4];
            ldsm4(ua, aPbase + ks * 32);
            #pragma unroll
            for (int vp = 0; vp < 4; vp++) {
                uint32_t vb[4];
                ldsm4(vb, bVbase[vp] + ks * 32);
                mma_f16(o[vp * 2 + 0], ua[0], ua[1], ua[2], ua[3], vb[0], vb[1]);
                mma_f16(o[vp * 2 + 1], ua[0], ua[1], ua[2], ua[3], vb[2], vb[3]);
            }
        }
    }

    /* final row-sum reduce: over t lanes, then over 4 warp-columns */
    ps0acc += __shfl_xor_sync(0xffffffffu, ps0acc, 1);
    ps0acc += __shfl_xor_sync(0xffffffffu, ps0acc, 2);
    ps1acc += __shfl_xor_sync(0xffffffffu, ps1acc, 1);
    ps1acc += __shfl_xor_sync(0xffffffffu, ps1acc, 2);
    __syncthreads();
    if (t == 0) { spart[wc * 64 + r0] = ps0acc; spart[wc * 64 + r1] = ps1acc; }
    __syncthreads();
    float il0 = 1.0f / (spart[r0] + spart[64 + r0] + spart[128 + r0] + spart[192 + r0]);
    float il1 = 1.0f / (spart[r1] + spart[64 + r1] + spart[128 + r1] + spart[192 + r1]);

    /* epilogue: normalize, add ELA, store */
    const float* xg = x + (size_t)b * CC * NPIX;
    float* og = out + (size_t)b * CC * NPIX;
    int i0 = m0 + g, i1 = i0 + 8;     /* w coords; h = qt */
    #pragma unroll
    for (int nt = 0; nt < 8; nt++) {
        #pragma unroll
        for (int bc = 0; bc < 2; bc++) {
            int d = d0 + nt * 8 + 2 * t + bc;
            float xh  = g_s[0][((size_t)b * CC + d) * 64 + qt];
            float xw0 = g_s[1][((size_t)b * CC + d) * 64 + i0];
            float xw1 = g_s[1][((size_t)b * CC + d) * 64 + i1];
            size_t base = (size_t)d * NPIX + n0;
            og[base + i0] = o[nt][bc]     * il0 + xg[base + i0] * xh * xw0;
            og[base + i1] = o[nt][2 + bc] * il1 + xg[base + i1] * xh * xw1;
        }
    }
}

/* ================= launch ================= */
extern "C" void kernel_launch(void* const* d_in, const int* in_sizes, int n_in,
                              void* d_out, int out_size) {
    const float* x     = (const float*)d_in[0];
    const float* wqkv  = (const float*)d_in[1];
    const float* w1    = (const float*)d_in[2];
    const float* b1    = (const float*)d_in[3];
    const float* gamma = (const float*)d_in[4];
    const float* beta  = (const float*)d_in[5];
    float* out = (float*)d_out;

    cudaFuncSetAttribute(gn_kernel, cudaFuncAttributeMaxDynamicSharedMemorySize,
                         (256 * 64 + 512) * 4);
    cudaFuncSetAttribute(qkv_kernel, cudaFuncAttributeMaxDynamicSharedMemorySize,
                         QKV_SMEM);
    cudaFuncSetAttribute(flash_kernel, cudaFuncAttributeMaxDynamicSharedMemorySize,
                         ATT_SMEM);

    means_kernel<<<BB * CC, 256>>>(x);
    gn_kernel<<<16, 256, (256 * 64 + 512) * 4>>>(w1, b1, gamma, beta);
    qkv_kernel<<<dim3(6, 32, BB), 256, QKV_SMEM>>>(x, wqkv);
    flash_kernel<<<dim3(64, BB), 512, ATT_SMEM>>>(x, out);
}

// round 17
// speedup vs baseline: 1.1796x; 1.0278x over previous
#include <cuda_runtime.h>
#include <cuda_fp16.h>
#include <math.h>
#include <stdint.h>

#define BB   8
#define CC   256
#define NPIX 4096
#define NGRP 16
#define SCALE 0.0625f   /* 256^-0.5 */

/* ---- scratch (static device globals: allocation-free) ---- */
__device__ __half g_qT[(size_t)BB * NPIX * CC];   /* Q^T: [b][pixel][ch] */
__device__ __half g_kT[(size_t)BB * NPIX * CC];   /* K^T: [b][pixel][ch] */
__device__ __half g_v [(size_t)BB * CC * NPIX];   /* V:   [b][ch][pixel] */
__device__ float  g_y[2][BB * CC * 64];
__device__ float  g_s[2][BB * CC * 64];

__device__ __forceinline__ uint32_t h2u(__half2 h) {
    return *(uint32_t*)&h;
}
__device__ __forceinline__ void mma_f16(float* d,
                                        uint32_t a0, uint32_t a1, uint32_t a2, uint32_t a3,
                                        uint32_t b0, uint32_t b1) {
    asm volatile(
        "mma.sync.aligned.m16n8k16.row.col.f32.f16.f16.f32 "
        "{%0,%1,%2,%3}, {%4,%5,%6,%7}, {%8,%9}, {%0,%1,%2,%3};\n"
        : "+f"(d[0]), "+f"(d[1]), "+f"(d[2]), "+f"(d[3])
        : "r"(a0), "r"(a1), "r"(a2), "r"(a3), "r"(b0), "r"(b1));
}
__device__ __forceinline__ void ldsm4(uint32_t* r, uint32_t saddr) {
    asm volatile(
        "ldmatrix.sync.aligned.m8n8.x4.shared.b16 {%0,%1,%2,%3}, [%4];"
        : "=r"(r[0]), "=r"(r[1]), "=r"(r[2]), "=r"(r[3]) : "r"(saddr));
}
__device__ __forceinline__ void ldsm4t(uint32_t* r, uint32_t saddr) {
    asm volatile(
        "ldmatrix.sync.aligned.m8n8.x4.trans.shared.b16 {%0,%1,%2,%3}, [%4];"
        : "=r"(r[0]), "=r"(r[1]), "=r"(r[2]), "=r"(r[3]) : "r"(saddr));
}
__device__ __forceinline__ uint32_t sptr(const void* p) {
    return (uint32_t)__cvta_generic_to_shared(p);
}

/* ================= 1. row/col means ================= */
__global__ void __launch_bounds__(256) means_kernel(const float* __restrict__ x) {
    __shared__ float tile[64][65];
    int bc = blockIdx.x;
    const float* xp = x + (size_t)bc * NPIX;
    int tid = threadIdx.x;
    #pragma unroll
    for (int t = 0; t < 16; t++) {
        int idx = tid + t * 256;
        tile[idx >> 6][idx & 63] = xp[idx];
    }
    __syncthreads();
    if (tid < 64) {
        float s = 0.f;
        #pragma unroll
        for (int w = 0; w < 64; w++) s += tile[tid][w];
        g_y[0][(size_t)bc * 64 + tid] = s * (1.0f / 64.0f);
    } else if (tid < 128) {
        int w = tid - 64;
        float s = 0.f;
        #pragma unroll
        for (int h = 0; h < 64; h++) s += tile[h][w];
        g_y[1][(size_t)bc * 64 + w] = s * (1.0f / 64.0f);
    }
}

/* ================= 2. GN + sigmoid branch ================= */
__global__ void __launch_bounds__(256) gn_kernel(const float* __restrict__ w1,
                                                 const float* __restrict__ b1,
                                                 const float* __restrict__ gamma,
                                                 const float* __restrict__ beta) {
    extern __shared__ float sm[];
    float* ys  = sm;
    float* red = sm + 256 * 64;
    __shared__ float mu_s[NGRP], rs_s[NGRP];

    int br = blockIdx.x >> 3;
    int b  = blockIdx.x & 7;
    const float* y = g_y[br] + (size_t)b * CC * 64;
    int tid = threadIdx.x;

    #pragma unroll
    for (int t = 0; t < 16; t++) {
        int i4 = tid + t * 256;
        ((float4*)ys)[i4] = ((const float4*)y)[i4];
    }
    __syncthreads();

    float acc[64];
    #pragma unroll
    for (int l = 0; l < 64; l++) acc[l] = 0.f;

    const float* w1r = w1 + (size_t)tid * CC;
    for (int c = 0; c < CC; c++) {
        float wv = w1r[c];
        const float4* yr = (const float4*)(ys + c * 64);
        #pragma unroll
        for (int l4 = 0; l4 < 16; l4++) {
            float4 yv = yr[l4];
            acc[l4 * 4 + 0] += wv * yv.x;
            acc[l4 * 4 + 1] += wv * yv.y;
            acc[l4 * 4 + 2] += wv * yv.z;
            acc[l4 * 4 + 3] += wv * yv.w;
        }
    }
    float bias = b1[tid];
    float s1 = 0.f, s2 = 0.f;
    #pragma unroll
    for (int l = 0; l < 64; l++) {
        acc[l] += bias;
        s1 += acc[l];
        s2 += acc[l] * acc[l];
    }
    red[tid]       = s1;
    red[256 + tid] = s2;
    __syncthreads();
    if (tid < NGRP) {
        float S = 0.f, S2 = 0.f;
        #pragma unroll
        for (int k = 0; k < 16; k++) {
            S  += red[tid * 16 + k];
            S2 += red[256 + tid * 16 + k];
        }
        float mu  = S * (1.0f / 1024.0f);
        float var = S2 * (1.0f / 1024.0f) - mu * mu;
        mu_s[tid] = mu;
        rs_s[tid] = rsqrtf(var + 1e-5f);
    }
    __syncthreads();
    float mu = mu_s[tid >> 4], rs = rs_s[tid >> 4];
    float ga = gamma[tid], be = beta[tid];
    float* o = g_s[br] + ((size_t)b * CC + tid) * 64;
    #pragma unroll
    for (int l = 0; l < 64; l++) {
        float zn = (acc[l] - mu) * rs;
        float v  = zn * ga + be;
        o[l] = 1.0f / (1.0f + __expf(-v));
    }
}

/* ================= 3. QKV projection (fp16 HMMA, ldmatrix operands) ========
   grid (6, 32, 8); block 256 = 8 warps (warp grid 2m x 4n); tile 128x128.
   Ws [m][k] pitch 264; Xs NATURAL [k][n] pitch 136 (coalesced stores);
   W frags via ldmatrix, X frags via ldmatrix.trans.                       */
#define WPH 264
#define XPH 136
#define QKV_SMEM (128 * WPH * 2 + 256 * XPH * 2)   /* 67584 + 69632 = 137216 */

__global__ void __launch_bounds__(256) qkv_kernel(const float* __restrict__ x,
                                                  const float* __restrict__ wq) {
    extern __shared__ __half smh[];
    __half* Ws = smh;                 /* [128 m][WPH k] */
    __half* Xs = smh + 128 * WPH;     /* [256 k][XPH n] */
    int mtb = blockIdx.x, ntb = blockIdx.y, b = blockIdx.z;
    int m0 = mtb * 128, n0 = ntb * 128;
    const float* X = x + (size_t)b * CC * NPIX;
    int tid = threadIdx.x;
    int lane = tid & 31, wid = tid >> 5;
    int g = lane >> 2, t = lane & 3;
    int lrow8 = lane & 7, lrhi = (lane >> 3) & 1, lchi = lane >> 4;

    /* ---- load W tile, convert fp16, [m][k] (coalesced) ---- */
    {
        int row = tid >> 1, ks = (tid & 1) * 128;
        const float* src = wq + (size_t)(m0 + row) * CC + ks;
        __half* dst = Ws + row * WPH + ks;
        #pragma unroll
        for (int i = 0; i < 32; i++) {
            float4 w = *(const float4*)(src + i * 4);
            uint2 p;
            p.x = h2u(__floats2half2_rn(w.x, w.y));
            p.y = h2u(__floats2half2_rn(w.z, w.w));
            *(uint2*)(dst + i * 4) = p;
        }
    }
    /* ---- load X tile NATURAL [k][n], convert fp16 (coalesced LDG+STS) ---- */
    #pragma unroll
    for (int it = 0; it < 32; it++) {
        int idx = tid + it * 256;          /* 8192 float4s */
        int k = idx >> 5, n = (idx & 31) * 4;
        float4 v = *(const float4*)(X + (size_t)k * NPIX + n0 + n);
        uint2 p;
        p.x = h2u(__floats2half2_rn(v.x, v.y));
        p.y = h2u(__floats2half2_rn(v.z, v.w));
        *(uint2*)(Xs + k * XPH + n) = p;
    }
    __syncthreads();

    int wm = wid & 1, wn = wid >> 1;
    int mw0 = wm * 64, nw0 = wn * 32;

    /* fragment base addresses */
    uint32_t awbase[4];
    #pragma unroll
    for (int mt = 0; mt < 4; mt++)
        awbase[mt] = sptr(Ws + (mw0 + mt * 16 + lrow8 + lrhi * 8) * WPH + lchi * 8);
    /* X trans-frag: lanes 0-7 rows k0-7 @ n, 8-15 k8-15 @ n, 16-23 k0-7 @ n+8,
       24-31 k8-15 @ n+8  → regs (k0,n0),(k8,n0),(k0,n8),(k8,n8) transposed */
    uint32_t bxbase[2];
    #pragma unroll
    for (int ntp = 0; ntp < 2; ntp++)
        bxbase[ntp] = sptr(Xs + (lrow8 + lrhi * 8) * XPH + nw0 + ntp * 16 + lchi * 8);

    float acc[4][4][4];
    #pragma unroll
    for (int mt = 0; mt < 4; mt++)
        #pragma unroll
        for (int nt = 0; nt < 4; nt++)
            #pragma unroll
            for (int e = 0; e < 4; e++) acc[mt][nt][e] = 0.f;

    #pragma unroll 4
    for (int ks = 0; ks < 16; ks++) {
        uint32_t bfr[2][4];
        ldsm4t(bfr[0], bxbase[0] + ks * 16 * XPH * 2);
        ldsm4t(bfr[1], bxbase[1] + ks * 16 * XPH * 2);
        #pragma unroll
        for (int mt = 0; mt < 4; mt++) {
            uint32_t a[4];
            ldsm4(a, awbase[mt] + ks * 32);
            mma_f16(acc[mt][0], a[0], a[1], a[2], a[3], bfr[0][0], bfr[0][1]);
            mma_f16(acc[mt][1], a[0], a[1], a[2], a[3], bfr[0][2], bfr[0][3]);
            mma_f16(acc[mt][2], a[0], a[1], a[2], a[3], bfr[1][0], bfr[1][1]);
            mma_f16(acc[mt][3], a[0], a[1], a[2], a[3], bfr[1][2], bfr[1][3]);
        }
    }

    /* ---- epilogue ---- */
    if (m0 < 512) {
        __half* dstb = (m0 < 256 ? g_qT : g_kT) + (size_t)b * NPIX * CC;
        int chb = (m0 & 255) + mw0;
        #pragma unroll
        for (int mt = 0; mt < 4; mt++) {
            int ch = chb + mt * 16 + g;
            #pragma unroll
            for (int nt = 0; nt < 4; nt++) {
                int n = n0 + nw0 + nt * 8 + 2 * t;
                dstb[(size_t)n * CC + ch]           = __float2half_rn(acc[mt][nt][0]);
                dstb[(size_t)(n + 1) * CC + ch]     = __float2half_rn(acc[mt][nt][1]);
                dstb[(size_t)n * CC + ch + 8]       = __float2half_rn(acc[mt][nt][2]);
                dstb[(size_t)(n + 1) * CC + ch + 8] = __float2half_rn(acc[mt][nt][3]);
            }
        }
    } else {
        __half* dstb = g_v + (size_t)b * CC * NPIX;
        int chb = (m0 - 512) + mw0;
        #pragma unroll
        for (int mt = 0; mt < 4; mt++) {
            int ch = chb + mt * 16 + g;
            #pragma unroll
            for (int nt = 0; nt < 4; nt++) {
                int n = n0 + nw0 + nt * 8 + 2 * t;
                *(__half2*)(dstb + (size_t)ch * NPIX + n) =
                    __floats2half2_rn(acc[mt][nt][0], acc[mt][nt][1]);
                *(__half2*)(dstb + (size_t)(ch + 8) * NPIX + n) =
                    __floats2half2_rn(acc[mt][nt][2], acc[mt][nt][3]);
            }
        }
    }
}

/* ================= 4. flash attention (512 thr, ldmatrix fragments) ======== */
#define QPH 264   /* halves */
#define KPH 264
#define VPH 136
#define PPH 136
#define SM_Q   0                                 /* 64*264*2   = 33792 */
#define SM_K   33792                             /* 128*264*2  = 67584 */
#define SM_V   101376                            /* 256*136*2  = 69632 */
#define SM_P   171008                            /* 64*136*2   = 17408 */
#define SM_SPB 188416                            /* float[4][64] = 1024 */
#define ATT_SMEM 189440

__device__ __forceinline__ void cp16h(void* dst_smem, const void* src) {
    uint32_t d = (uint32_t)__cvta_generic_to_shared(dst_smem);
    asm volatile("cp.async.cg.shared.global [%0], [%1], 16;" :: "r"(d), "l"(src));
}
#define CP_COMMIT() asm volatile("cp.async.commit_group;" ::: "memory")
#define CP_WAIT1()  asm volatile("cp.async.wait_group 1;" ::: "memory")
#define CP_WAIT0()  asm volatile("cp.async.wait_group 0;" ::: "memory")

__global__ void __launch_bounds__(512) flash_kernel(const float* __restrict__ x,
                                                    float* __restrict__ out) {
    extern __shared__ char smc[];
    __half* QsT = (__half*)(smc + SM_Q);
    __half* KsT = (__half*)(smc + SM_K);
    __half* Vs  = (__half*)(smc + SM_V);
    __half* Ps  = (__half*)(smc + SM_P);
    float* spart = (float*)(smc + SM_SPB);

    int qt = blockIdx.x, b = blockIdx.y;
    int n0 = qt * 64;
    const __half* qTg = g_qT + (size_t)b * NPIX * CC;
    const __half* kTg = g_kT + (size_t)b * NPIX * CC;
    const __half* vg  = g_v  + (size_t)b * CC * NPIX;

    int tid  = threadIdx.x;
    int lane = tid & 31;
    int wid  = tid >> 5;
    int g = lane >> 2, t = lane & 3;
    int wr = wid & 3, wc = wid >> 2;
    int m0  = wr * 16;
    int nn0 = wc * 32;
    int d0  = wc * 64;

    int lrow8 = lane & 7;
    int lrhi  = (lane >> 3) & 1;
    int lchi  = lane >> 4;

    uint32_t aQbase = sptr(QsT + (m0 + lrow8 + lrhi * 8) * QPH + lchi * 8);
    uint32_t aPbase = sptr(Ps  + (m0 + lrow8 + lrhi * 8) * PPH + lchi * 8);
    uint32_t bKbase0 = sptr(KsT + (nn0 +  0 + lchi * 8 + lrow8) * KPH + lrhi * 8);
    uint32_t bKbase1 = sptr(KsT + (nn0 + 16 + lchi * 8 + lrow8) * KPH + lrhi * 8);
    uint32_t bVbase[4];
    #pragma unroll
    for (int vp = 0; vp < 4; vp++)
        bVbase[vp] = sptr(Vs + (d0 + vp * 16 + lchi * 8 + lrow8) * VPH + lrhi * 8);

    /* prefetch Q tile + K(0) tile (one group) */
    #pragma unroll
    for (int it = 0; it < 4; it++) {
        int idx = tid + it * 512;
        int r = idx >> 5, ch = idx & 31;
        cp16h(QsT + r * QPH + ch * 8, qTg + (size_t)(n0 + r) * CC + ch * 8);
    }
    #pragma unroll
    for (int it = 0; it < 8; it++) {
        int idx = tid + it * 512;
        int r = idx >> 5, ch = idx & 31;
        cp16h(KsT + r * KPH + ch * 8, kTg + (size_t)r * CC + ch * 8);
    }
    CP_COMMIT();

    float o[8][4];
    #pragma unroll
    for (int nt = 0; nt < 8; nt++)
        #pragma unroll
        for (int e = 0; e < 4; e++) o[nt][e] = 0.f;
    float ps0acc = 0.f, ps1acc = 0.f;

    int r0 = m0 + g, r1 = r0 + 8;

    for (int kt = 0; kt < 32; kt++) {
        int km0 = kt * 128;
        __syncthreads();                       /* A: prev PV done; V/Ps free */

        #pragma unroll
        for (int it = 0; it < 8; it++) {
            int idx = tid + it * 512;
            int d = idx >> 4, ch = idx & 15;
            cp16h(Vs + d * VPH + ch * 8, vg + (size_t)d * NPIX + km0 + ch * 8);
        }
        CP_COMMIT();
        CP_WAIT1();                            /* K(kt) arrived */
        __syncthreads();                       /* B: K visible to all warps */

        /* ---- S = Q^T K: 16 rows x 32 cols per warp, ldmatrix frags ---- */
        float sacc[4][4];
        #pragma unroll
        for (int nt = 0; nt < 4; nt++)
            #pragma unroll
            for (int e = 0; e < 4; e++) sacc[nt][e] = 0.f;

        #pragma unroll 8
        for (int ks = 0; ks < 16; ks++) {
            uint32_t a[4], b0[4], b1[4];
            ldsm4(a,  aQbase  + ks * 32);
            ldsm4(b0, bKbase0 + ks * 32);
            ldsm4(b1, bKbase1 + ks * 32);
            mma_f16(sacc[0], a[0], a[1], a[2], a[3], b0[0], b0[1]);
            mma_f16(sacc[1], a[0], a[1], a[2], a[3], b0[2], b0[3]);
            mma_f16(sacc[2], a[0], a[1], a[2], a[3], b1[0], b1[1]);
            mma_f16(sacc[3], a[0], a[1], a[2], a[3], b1[2], b1[3]);
        }

        /* ---- fixed-max softmax: p = exp(SCALE*s) ---- */
        #pragma unroll
        for (int nt = 0; nt < 4; nt++) {
            int col = nn0 + nt * 8 + 2 * t;
            __half2 h0 = __floats2half2_rn(__expf(SCALE * sacc[nt][0]),
                                           __expf(SCALE * sacc[nt][1]));
            __half2 h1 = __floats2half2_rn(__expf(SCALE * sacc[nt][2]),
                                           __expf(SCALE * sacc[nt][3]));
            *(__half2*)(Ps + r0 * PPH + col) = h0;
            *(__half2*)(Ps + r1 * PPH + col) = h1;
            float2 f0 = __half22float2(h0);
            float2 f1 = __half22float2(h1);
            ps0acc += f0.x + f0.y;
            ps1acc += f1.x + f1.y;
        }

        CP_WAIT0();                            /* V(kt) arrived */
        __syncthreads();                       /* D: Ps + V visible; K consumed */

        /* issue K(kt+1) — overlaps PV */
        {
            int kn = (kt + 1 < 32) ? (kt + 1) * 128 : 0;
            #pragma unroll
            for (int it = 0; it < 8; it++) {
                int idx = tid + it * 512;
                int r = idx >> 5, ch = idx & 31;
                cp16h(KsT + r * KPH + ch * 8, kTg + (size_t)(kn + r) * CC + ch * 8);
            }
            CP_COMMIT();
        }

        /* ---- PV mma (K-dim 128), ldmatrix frags ---- */
        #pragma unroll
        for (int ks = 0; ks < 8; ks++) {
            uint32_t ua[4];
            ldsm4(ua, aPbase + ks * 32);
            #pragma unroll
            for (int vp = 0; vp < 4; vp++) {
                uint32_t vb[4];
                ldsm4(vb, bVbase[vp] + ks * 32);
                mma_f16(o[vp * 2 + 0], ua[0], ua[1], ua[2], ua[3], vb[0], vb[1]);
                mma_f16(o[vp * 2 + 1], ua[0], ua[1], ua[2], ua[3], vb[2], vb[3]);
            }
        }
    }

    /* final row-sum reduce: over t lanes, then over 4 warp-columns */
    ps0acc += __shfl_xor_sync(0xffffffffu, ps0acc, 1);
    ps0acc += __shfl_xor_sync(0xffffffffu, ps0acc, 2);
    ps1acc += __shfl_xor_sync(0xffffffffu, ps1acc, 1);
    ps1acc += __shfl_xor_sync(0xffffffffu, ps1acc, 2);
    __syncthreads();
    if (t == 0) { spart[wc * 64 + r0] = ps0acc; spart[wc * 64 + r1] = ps1acc; }
    __syncthreads();
    float il0 = 1.0f / (spart[r0] + spart[64 + r0] + spart[128 + r0] + spart[192 + r0]);
    float il1 = 1.0f / (spart[r1] + spart[64 + r1] + spart[128 + r1] + spart[192 + r1]);

    /* epilogue: normalize, add ELA, store */
    const float* xg = x + (size_t)b * CC * NPIX;
    float* og = out + (size_t)b * CC * NPIX;
    int i0 = m0 + g, i1 = i0 + 8;     /* w coords; h = qt */
    #pragma unroll
    for (int nt = 0; nt < 8; nt++) {
        #pragma unroll
        for (int bc = 0; bc < 2; bc++) {
            int d = d0 + nt * 8 + 2 * t + bc;
            float xh  = g_s[0][((size_t)b * CC + d) * 64 + qt];
            float xw0 = g_s[1][((size_t)b * CC + d) * 64 + i0];
            float xw1 = g_s[1][((size_t)b * CC + d) * 64 + i1];
            size_t base = (size_t)d * NPIX + n0;
            og[base + i0] = o[nt][bc]     * il0 + xg[base + i0] * xh * xw0;
            og[base + i1] = o[nt][2 + bc] * il1 + xg[base + i1] * xh * xw1;
        }
    }
}

/* ================= launch ================= */
extern "C" void kernel_launch(void* const* d_in, const int* in_sizes, int n_in,
                              void* d_out, int out_size) {
    const float* x     = (const float*)d_in[0];
    const float* wqkv  = (const float*)d_in[1];
    const float* w1    = (const float*)d_in[2];
    const float* b1    = (const float*)d_in[3];
    const float* gamma = (const float*)d_in[4];
    const float* beta  = (const float*)d_in[5];
    float* out = (float*)d_out;

    cudaFuncSetAttribute(gn_kernel, cudaFuncAttributeMaxDynamicSharedMemorySize,
                         (256 * 64 + 512) * 4);
    cudaFuncSetAttribute(qkv_kernel, cudaFuncAttributeMaxDynamicSharedMemorySize,
                         QKV_SMEM);
    cudaFuncSetAttribute(flash_kernel, cudaFuncAttributeMaxDynamicSharedMemorySize,
                         ATT_SMEM);

    means_kernel<<<BB * CC, 256>>>(x);
    gn_kernel<<<16, 256, (256 * 64 + 512) * 4>>>(w1, b1, gamma, beta);
    qkv_kernel<<<dim3(6, 32, BB), 256, QKV_SMEM>>>(x, wqkv);
    flash_kernel<<<dim3(64, BB), 512, ATT_SMEM>>>(x, out);
}